// round 2
// baseline (speedup 1.0000x reference)
#include <cuda_runtime.h>
#include <cstdint>

// Problem constants (fixed by the reference).
#define BB 32
#define TT 4096
#define DD 128
#define CHUNK 64
#define CC (TT / CHUNK)      // 64 chunks per batch
#define NBLK (BB * CC)       // 2048 blocks for phase 1 / 3
#define NAGG (BB * CC * DD)  // 262144 aggregate slots

// Scratch: per-chunk aggregates and resolved incoming states.
// fwd: (last_x, last_t, has, -) ; bwd: (first_x, first_t, has, -)
__device__ float4 g_fwd[NAGG];
__device__ float4 g_bwd[NAGG];
// Incoming state per chunk, defaults already folded in (x_last,t_last)/(x_next,t_next)
__device__ float2 g_pre[NAGG];
__device__ float2 g_suf[NAGG];

// ---------------------------------------------------------------------------
// Phase 1: per-chunk forward aggregate (last observed) and backward aggregate
// (first observed) per channel. One block = (b, chunk), one thread = d.
// Mask arrives as int32 (harness promotes bool -> int32).
// ---------------------------------------------------------------------------
__global__ __launch_bounds__(DD) void phase1(const float* __restrict__ v,
                                             const float* __restrict__ t,
                                             const int* __restrict__ m) {
    int lin = blockIdx.x;          // b*CC + c
    int b = lin / CC, c = lin % CC;
    int d = threadIdx.x;
    int base = (b * TT + c * CHUNK) * DD + d;

    float lx = 0.f, lt = 0.f;      // last observed in chunk
    float fx = 0.f, ft = 0.f;      // first observed in chunk
    float has = 0.f;

#pragma unroll 8
    for (int i = 0; i < CHUNK; i++) {
        int idx = base + i * DD;
        float vv = v[idx];
        float tt = t[idx];
        bool mm = (m[idx] != 0);
        if (mm) {
            if (has == 0.f) { fx = vv; ft = tt; }
            lx = vv; lt = tt; has = 1.f;
        }
    }
    int o = lin * DD + d;
    g_fwd[o] = make_float4(lx, lt, has, 0.f);
    g_bwd[o] = make_float4(fx, ft, has, 0.f);
}

// ---------------------------------------------------------------------------
// Phase 2: cross-chunk exclusive prefix (forward) and exclusive suffix
// (backward) scans per channel. Defaults (x=0, t=times[b,0,d] / times[b,T-1,d])
// are folded so phase 3 needs no has-flags. Grid: B blocks x D threads.
// ---------------------------------------------------------------------------
__global__ __launch_bounds__(DD) void phase2(const float* __restrict__ t) {
    int b = blockIdx.x, d = threadIdx.x;
    float t0   = t[(b * TT) * DD + d];
    float tmax = t[(b * TT + TT - 1) * DD + d];  // times strictly increasing

    float x = 0.f, tc = t0;
    for (int c = 0; c < CC; c++) {
        int o = (b * CC + c) * DD + d;
        g_pre[o] = make_float2(x, tc);
        float4 a = g_fwd[o];
        if (a.z != 0.f) { x = a.x; tc = a.y; }
    }
    x = 0.f; tc = tmax;
    for (int c = CC - 1; c >= 0; c--) {
        int o = (b * CC + c) * DD + d;
        g_suf[o] = make_float2(x, tc);
        float4 a = g_bwd[o];
        if (a.z != 0.f) { x = a.x; tc = a.y; }
    }
}

// ---------------------------------------------------------------------------
// Phase 3: local rescan + interpolation. Forward pass fills per-step
// (x_last, t_last) into smem (thread-private columns, no syncthreads needed),
// backward pass keeps (x_next, t_next) in registers, interpolates, writes.
// Blocks are walked in REVERSE bid order so the re-read hits the data phase 1
// left newest in L2. Output stores use streaming hint to avoid evicting input.
// ---------------------------------------------------------------------------
__global__ __launch_bounds__(DD) void phase3(const float* __restrict__ v,
                                             const float* __restrict__ t,
                                             const int* __restrict__ m,
                                             float* __restrict__ out) {
    extern __shared__ float2 fill[];   // [CHUNK][DD]
    int lin = (NBLK - 1) - blockIdx.x; // reverse order for L2 reuse
    int b = lin / CC, c = lin % CC;
    int d = threadIdx.x;
    int base = (b * TT + c * CHUNK) * DD + d;
    int o = lin * DD + d;

    float2 pre = g_pre[o];
    float xl = pre.x, tl = pre.y;

#pragma unroll 4
    for (int i = 0; i < CHUNK; i++) {
        int idx = base + i * DD;
        float vv = v[idx];
        float tt = t[idx];
        bool mm = (m[idx] != 0);
        if (mm) { xl = vv; tl = tt; }
        fill[i * DD + d] = make_float2(xl, tl);
    }

    float2 suf = g_suf[o];
    float xn = suf.x, tn = suf.y;

#pragma unroll 4
    for (int i = CHUNK - 1; i >= 0; i--) {
        int idx = base + i * DD;
        float vv = v[idx];
        float tt = t[idx];
        bool mm = (m[idx] != 0);
        if (mm) { xn = vv; tn = tt; }
        float2 f = fill[i * DD + d];
        float denom = tn - f.y;
        float num = f.x * (tn - tt) + xn * (tt - f.y);
        float itp = (denom != 0.f) ? (num / denom) : 0.f;
        float res = mm ? vv : itp;
        __stcs(&out[idx], res);    // streaming store: don't evict hot input
    }
}

// ---------------------------------------------------------------------------
extern "C" void kernel_launch(void* const* d_in, const int* in_sizes, int n_in,
                              void* d_out, int out_size) {
    const float* v = (const float*)d_in[0];
    const float* t = (const float*)d_in[1];
    const int*   m = (const int*)d_in[2];
    float* out = (float*)d_out;

    const int smem = CHUNK * DD * (int)sizeof(float2);  // 64 KB
    cudaFuncSetAttribute(phase3, cudaFuncAttributeMaxDynamicSharedMemorySize, smem);

    phase1<<<NBLK, DD>>>(v, t, m);
    phase2<<<BB, DD>>>(t);
    phase3<<<NBLK, DD, smem>>>(v, t, m, out);
}